// round 16
// baseline (speedup 1.0000x reference)
#include <cuda_runtime.h>
#include <math.h>

// ViT fused R16 = R15 (best, 281.3us) + latency-chain fixes:
//   (a) G1 manual unroll x2 (overlap LDS chains of adjacent j)
//   (b) FC1 4 independent accumulators (8-serial-FMA chain -> ~2)

#define GRP  16
#define NTHR 256

static constexpr int SM_PB  = 0;        // 16*784 = 12544
static constexpr int SM_PE  = 12544;    // 784
static constexpr int SM_QB  = 13328;    // 16*144 = 2304; QB%32 = 16
static constexpr int SM_KB  = 15648;    // KB%32 = 0
static constexpr int SM_F2W = 17952;    // 160
static constexpr int SM_F1B = 18112;    // 16
static constexpr int SM_F2B = 18128;    // 16
static constexpr int SM_H   = 18144;    // 256
static constexpr int SM_LG  = 18400;    // 256
static constexpr int SM_TOT = 18656;    // 74624 B -> 3 CTAs/SM
static constexpr int KB2    = SM_KB + 24;

__device__ __forceinline__ float dot4(float4 w, float4 a, float acc) {
    acc = fmaf(w.x, a.x, acc); acc = fmaf(w.y, a.y, acc);
    acc = fmaf(w.z, a.z, acc); return fmaf(w.w, a.w, acc);
}

__global__ __launch_bounds__(NTHR, 3)
void vit_fused_kernel(
    const float* __restrict__ x, const float* __restrict__ pos_emb,
    const float* __restrict__ WQ1, const float* __restrict__ WK1, const float* __restrict__ WV1,
    const float* __restrict__ WQ2, const float* __restrict__ WK2, const float* __restrict__ WV2,
    const float* __restrict__ fc1w, const float* __restrict__ fc1b,
    const float* __restrict__ fc2w, const float* __restrict__ fc2b,
    float* __restrict__ out, int B)
{
    extern __shared__ float sh[];
    const int tid  = threadIdx.x;
    const int lane = tid & 31;
    const int wrp  = tid >> 5;          // 0..7 : patch slot in P-phases
    const int t    = tid & 15;          // dim within sample
    const int ls   = tid >> 4;          // sample slot
    const int b0   = blockIdx.x * GRP;
    const int b    = b0 + ls;
    const float INV7 = 0.14285714285714285f;
    float* myrow = &sh[SM_PB + ls * 784];

    // ---------------- phase 0: patchify + constants ----------------
    for (int idx = tid; idx < GRP * 784; idx += NTHR) {
        int lsi = idx / 784, pix = idx - lsi * 784;
        int bb = b0 + lsi;
        float g = 0.f;
        if (bb < B) {
            const float* xp = x + (size_t)bb * 2352 + pix;
            g = 0.299f * xp[0] + 0.587f * xp[784] + 0.114f * xp[1568];
        }
        int y = pix / 28, xx = pix - y * 28;
        sh[SM_PB + lsi * 784 + ((y >> 2) * 7 + (xx >> 2)) * 16 + (y & 3) * 4 + (xx & 3)] = g;
    }
    for (int idx = tid; idx < 784; idx += NTHR) sh[SM_PE + idx] = pos_emb[idx];
    if (tid < 160) sh[SM_F2W + tid] = fc2w[tid];
    if (tid < 16)  sh[SM_F1B + tid] = fc1b[tid];
    if (tid < 10)  sh[SM_F2B + tid] = fc2b[tid];

    // ---------------- layer 1: chunks of 8 patches ----------------
    float S1[16];
#pragma unroll
    for (int e = 0; e < 16; e++) S1[e] = 0.f;

#pragma unroll 1
    for (int c0 = 0; c0 < 49; c0 += 8) {
        const int np = min(8, 49 - c0);
        __syncthreads();
        float vacc[8];
        const int s   = c0 + wrp;
        const int row = lane & 15;
        const int par = lane >> 4;          // sample parity for V pass
        // ---- P-phase ----
        if (wrp < np) {
            const float4* pe4 = reinterpret_cast<const float4*>(&sh[SM_PE + s * 16]);
            float4 p0 = pe4[0], p1 = pe4[1], p2 = pe4[2], p3 = pe4[3];
            // pass A: lanes 0-15 Q rows, 16-31 K rows; all 16 samples (broadcast tok)
            {
                const float* Wp = ((lane < 16) ? WQ1 : WK1) + s * 512 + row * 32;
                const float4* W4 = reinterpret_cast<const float4*>(Wp);
                float4 w0 = W4[0], w1 = W4[1], w2 = W4[2], w3 = W4[3];
                float pe_acc = dot4(W4[7], p3, dot4(W4[6], p2, dot4(W4[5], p1, dot4(W4[4], p0, 0.f))));
                const float scl = (lane < 16) ? INV7 : 1.f;
                const int dst = ((lane < 16) ? SM_QB : SM_KB) + wrp * 16 + row;
#pragma unroll 4
                for (int i = 0; i < 16; i++) {
                    const float4* tk = reinterpret_cast<const float4*>(&sh[SM_PB + i * 784 + s * 16]);
                    float acc = dot4(w3, tk[3], dot4(w2, tk[2], dot4(w1, tk[1], dot4(w0, tk[0], pe_acc))));
                    sh[dst + i * 144] = acc * scl;
                }
            }
            // pass B: V row = lane&15, sample parity split (bank-disjoint rows)
            {
                const float4* W4 = reinterpret_cast<const float4*>(WV1 + s * 512 + row * 32);
                float4 w0 = W4[0], w1 = W4[1], w2 = W4[2], w3 = W4[3];
                float pe_acc = dot4(W4[7], p3, dot4(W4[6], p2, dot4(W4[5], p1, dot4(W4[4], p0, 0.f))));
#pragma unroll 2
                for (int ii = 0; ii < 8; ii++) {
                    const int i = 2 * ii + par;
                    const float4* tk = reinterpret_cast<const float4*>(&sh[SM_PB + i * 784 + s * 16]);
                    vacc[ii] = dot4(w3, tk[3], dot4(w2, tk[2], dot4(w1, tk[1], dot4(w0, tk[0], pe_acc))));
                }
            }
        }
        __syncwarp();   // all patch-row reads complete before V overwrites
        if (wrp < np) {
#pragma unroll
            for (int ii = 0; ii < 8; ii++)
                sh[SM_PB + (2 * ii + par) * 784 + s * 16 + row] = vacc[ii];
        }
        __syncthreads();
        // ---- G-phase: warp = 2 samples, manual unroll x2 ----
        {
            int j = 0;
#pragma unroll 1
            for (; j + 1 < np; j += 2) {
                float qA = sh[SM_QB + ls * 144 + j * 16 + t];
                float qB = sh[SM_QB + ls * 144 + (j + 1) * 16 + t];
                const float4* krA = reinterpret_cast<const float4*>(&sh[SM_KB + ls * 144 + j * 16]);
                const float4* krB = reinterpret_cast<const float4*>(&sh[SM_KB + ls * 144 + (j + 1) * 16]);
                float4 a0 = krA[0], a1 = krA[1], a2 = krA[2], a3 = krA[3];
                float4 b0 = krB[0], b1 = krB[1], b2 = krB[2], b3 = krB[3];
                S1[0]  = fmaf(qA, a0.x, S1[0]);  S1[1]  = fmaf(qA, a0.y, S1[1]);
                S1[2]  = fmaf(qA, a0.z, S1[2]);  S1[3]  = fmaf(qA, a0.w, S1[3]);
                S1[4]  = fmaf(qA, a1.x, S1[4]);  S1[5]  = fmaf(qA, a1.y, S1[5]);
                S1[6]  = fmaf(qA, a1.z, S1[6]);  S1[7]  = fmaf(qA, a1.w, S1[7]);
                S1[8]  = fmaf(qA, a2.x, S1[8]);  S1[9]  = fmaf(qA, a2.y, S1[9]);
                S1[10] = fmaf(qA, a2.z, S1[10]); S1[11] = fmaf(qA, a2.w, S1[11]);
                S1[12] = fmaf(qA, a3.x, S1[12]); S1[13] = fmaf(qA, a3.y, S1[13]);
                S1[14] = fmaf(qA, a3.z, S1[14]); S1[15] = fmaf(qA, a3.w, S1[15]);
                S1[0]  = fmaf(qB, b0.x, S1[0]);  S1[1]  = fmaf(qB, b0.y, S1[1]);
                S1[2]  = fmaf(qB, b0.z, S1[2]);  S1[3]  = fmaf(qB, b0.w, S1[3]);
                S1[4]  = fmaf(qB, b1.x, S1[4]);  S1[5]  = fmaf(qB, b1.y, S1[5]);
                S1[6]  = fmaf(qB, b1.z, S1[6]);  S1[7]  = fmaf(qB, b1.w, S1[7]);
                S1[8]  = fmaf(qB, b2.x, S1[8]);  S1[9]  = fmaf(qB, b2.y, S1[9]);
                S1[10] = fmaf(qB, b2.z, S1[10]); S1[11] = fmaf(qB, b2.w, S1[11]);
                S1[12] = fmaf(qB, b3.x, S1[12]); S1[13] = fmaf(qB, b3.y, S1[13]);
                S1[14] = fmaf(qB, b3.z, S1[14]); S1[15] = fmaf(qB, b3.w, S1[15]);
            }
            if (j < np) {
                float q = sh[SM_QB + ls * 144 + j * 16 + t];
                const float4* kr = reinterpret_cast<const float4*>(&sh[SM_KB + ls * 144 + j * 16]);
                float4 k0 = kr[0], k1 = kr[1], k2 = kr[2], k3 = kr[3];
                S1[0]  = fmaf(q, k0.x, S1[0]);  S1[1]  = fmaf(q, k0.y, S1[1]);
                S1[2]  = fmaf(q, k0.z, S1[2]);  S1[3]  = fmaf(q, k0.w, S1[3]);
                S1[4]  = fmaf(q, k1.x, S1[4]);  S1[5]  = fmaf(q, k1.y, S1[5]);
                S1[6]  = fmaf(q, k1.z, S1[6]);  S1[7]  = fmaf(q, k1.w, S1[7]);
                S1[8]  = fmaf(q, k2.x, S1[8]);  S1[9]  = fmaf(q, k2.y, S1[9]);
                S1[10] = fmaf(q, k2.z, S1[10]); S1[11] = fmaf(q, k2.w, S1[11]);
                S1[12] = fmaf(q, k3.x, S1[12]); S1[13] = fmaf(q, k3.y, S1[13]);
                S1[14] = fmaf(q, k3.z, S1[14]); S1[15] = fmaf(q, k3.w, S1[15]);
            }
        }
    }

    // ---------------- A1: grouped compute -> syncwarp -> write (in place) ----------------
#pragma unroll 1
    for (int sb = 0; sb < 49; sb += 7) {
        float a[7];
#pragma unroll
        for (int u = 0; u < 7; u++) {
            const float4* vr = reinterpret_cast<const float4*>(&myrow[(sb + u) * 16]);
            float4 v0 = vr[0], v1 = vr[1], v2 = vr[2], v3 = vr[3];
            float a0 = 0.f, a1 = 0.f;
            a0 = fmaf(S1[0],  v0.x, a0); a1 = fmaf(S1[1],  v0.y, a1);
            a0 = fmaf(S1[2],  v0.z, a0); a1 = fmaf(S1[3],  v0.w, a1);
            a0 = fmaf(S1[4],  v1.x, a0); a1 = fmaf(S1[5],  v1.y, a1);
            a0 = fmaf(S1[6],  v1.z, a0); a1 = fmaf(S1[7],  v1.w, a1);
            a0 = fmaf(S1[8],  v2.x, a0); a1 = fmaf(S1[9],  v2.y, a1);
            a0 = fmaf(S1[10], v2.z, a0); a1 = fmaf(S1[11], v2.w, a1);
            a0 = fmaf(S1[12], v3.x, a0); a1 = fmaf(S1[13], v3.y, a1);
            a0 = fmaf(S1[14], v3.z, a0); a1 = fmaf(S1[15], v3.w, a1);
            a[u] = a0 + a1;
        }
        __syncwarp();
#pragma unroll
        for (int u = 0; u < 7; u++) myrow[(sb + u) * 16 + t] = a[u];
        __syncwarp();
    }

    // ---------------- softmax1: quadrant-rotated access ----------------
    {
        const int r = (t >> 1) & 3;
#pragma unroll 1
        for (int s = t; s < 49; s += 16) {
            float4* row = reinterpret_cast<float4*>(&myrow[s * 16]);
            const int i0 = r, i1 = (r + 1) & 3, i2 = (r + 2) & 3, i3 = (r + 3) & 3;
            float4 v0 = row[i0], v1 = row[i1], v2 = row[i2], v3 = row[i3];
            float m = fmaxf(fmaxf(fmaxf(v0.x, v0.y), fmaxf(v0.z, v0.w)),
                            fmaxf(fmaxf(v1.x, v1.y), fmaxf(v1.z, v1.w)));
            m = fmaxf(m, fmaxf(fmaxf(fmaxf(v2.x, v2.y), fmaxf(v2.z, v2.w)),
                               fmaxf(fmaxf(v3.x, v3.y), fmaxf(v3.z, v3.w))));
            v0.x = __expf(v0.x - m); v0.y = __expf(v0.y - m); v0.z = __expf(v0.z - m); v0.w = __expf(v0.w - m);
            v1.x = __expf(v1.x - m); v1.y = __expf(v1.y - m); v1.z = __expf(v1.z - m); v1.w = __expf(v1.w - m);
            v2.x = __expf(v2.x - m); v2.y = __expf(v2.y - m); v2.z = __expf(v2.z - m); v2.w = __expf(v2.w - m);
            v3.x = __expf(v3.x - m); v3.y = __expf(v3.y - m); v3.z = __expf(v3.z - m); v3.w = __expf(v3.w - m);
            float sum = (v0.x + v0.y + v0.z + v0.w) + (v1.x + v1.y + v1.z + v1.w)
                      + (v2.x + v2.y + v2.z + v2.w) + (v3.x + v3.y + v3.z + v3.w);
            float inv = 1.f / sum;
            v0.x *= inv; v0.y *= inv; v0.z *= inv; v0.w *= inv;
            v1.x *= inv; v1.y *= inv; v1.z *= inv; v1.w *= inv;
            v2.x *= inv; v2.y *= inv; v2.z *= inv; v2.w *= inv;
            v3.x *= inv; v3.y *= inv; v3.z *= inv; v3.w *= inv;
            row[i0] = v0; row[i1] = v1; row[i2] = v2; row[i3] = v3;
        }
    }

    // ---------------- layer 2: chunks of 8 patches ----------------
    float S2[8];
#pragma unroll
    for (int e = 0; e < 8; e++) S2[e] = 0.f;
    const int d8 = t & 7;
    const int jp = t >> 3;

#pragma unroll 1
    for (int c0 = 0; c0 < 49; c0 += 8) {
        const int np = min(8, 49 - c0);
        __syncthreads();
        float vacc[4];
        const int s   = c0 + wrp;
        const int rV  = lane & 7;
        const int qtr = lane >> 3;          // V-pass sample quarter
        if (wrp < np) {
            // pass A: 16 rows (8Q+8K) x parity-split sample halves -> full 32 lanes
            {
                const int row16 = lane & 15;
                const int parA  = lane >> 4;
                const bool isQ  = (row16 < 8);
                const int r = row16 & 7;
                const float4* W4 = reinterpret_cast<const float4*>(
                    (isQ ? WQ2 : WK2) + s * 128 + r * 16);
                float4 w0 = W4[0], w1 = W4[1], w2 = W4[2], w3 = W4[3];
                const float scl = isQ ? INV7 : 1.f;
                const int dst = (isQ ? SM_QB : KB2) + wrp * 8 + r;
#pragma unroll 2
                for (int ii = 0; ii < 8; ii++) {
                    const int i = 2 * ii + parA;
                    const float4* tk = reinterpret_cast<const float4*>(&sh[SM_PB + i * 784 + s * 16]);
                    float acc = dot4(w3, tk[3], dot4(w2, tk[2], dot4(w1, tk[1], dot4(w0, tk[0], 0.f))));
                    sh[dst + i * 80] = acc * scl;
                }
            }
            // pass B: V rows x interleaved sample quarters (deferred)
            {
                const float4* W4 = reinterpret_cast<const float4*>(WV2 + s * 128 + rV * 16);
                float4 w0 = W4[0], w1 = W4[1], w2 = W4[2], w3 = W4[3];
#pragma unroll
                for (int ii = 0; ii < 4; ii++) {
                    const int i = 4 * ii + qtr;
                    const float4* tk = reinterpret_cast<const float4*>(&sh[SM_PB + i * 784 + s * 16]);
                    vacc[ii] = dot4(w3, tk[3], dot4(w2, tk[2], dot4(w1, tk[1], dot4(w0, tk[0], 0.f))));
                }
            }
        }
        __syncwarp();   // all tok2 reads complete before V2 overwrites
        if (wrp < np) {
#pragma unroll
            for (int ii = 0; ii < 4; ii++)
                sh[SM_PB + (4 * ii + qtr) * 784 + s * 16 + rV] = vacc[ii];
        }
        __syncthreads();
        // ---- G-phase: j split by t-parity (t<8 even j, t>=8 odd j) ----
#pragma unroll
        for (int jj = 0; jj < 4; jj++) {
            const int j = 2 * jj + jp;
            if (j < np) {
                float q2 = sh[SM_QB + ls * 80 + j * 8 + d8];
                const float4* kr = reinterpret_cast<const float4*>(&sh[KB2 + ls * 80 + j * 8]);
                float4 k0 = kr[0], k1 = kr[1];
                S2[0] = fmaf(q2, k0.x, S2[0]); S2[1] = fmaf(q2, k0.y, S2[1]);
                S2[2] = fmaf(q2, k0.z, S2[2]); S2[3] = fmaf(q2, k0.w, S2[3]);
                S2[4] = fmaf(q2, k1.x, S2[4]); S2[5] = fmaf(q2, k1.y, S2[5]);
                S2[6] = fmaf(q2, k1.z, S2[6]); S2[7] = fmaf(q2, k1.w, S2[7]);
            }
        }
    }
    // combine gram partials across j-parity halves (same sample)
#pragma unroll
    for (int e = 0; e < 8; e++) S2[e] += __shfl_xor_sync(0xffffffffu, S2[e], 8);

    // ---------------- A2: row-parity split across lane halves (25 iters) ----------------
#pragma unroll 1
    for (int ub = 0; ub < 25; ub += 7) {
        float a[7];
#pragma unroll
        for (int u2 = 0; u2 < 7; u2++) {
            const int u = ub + u2;
            const int srow = 2 * u + jp;
            float acc = 0.f;
            if (u < 25 && srow < 49) {
                const float4* vr = reinterpret_cast<const float4*>(&myrow[srow * 16]);
                float4 v0 = vr[0], v1 = vr[1];
                acc = fmaf(S2[0], v0.x, acc); acc = fmaf(S2[1], v0.y, acc);
                acc = fmaf(S2[2], v0.z, acc); acc = fmaf(S2[3], v0.w, acc);
                acc = fmaf(S2[4], v1.x, acc); acc = fmaf(S2[5], v1.y, acc);
                acc = fmaf(S2[6], v1.z, acc); acc = fmaf(S2[7], v1.w, acc);
            }
            a[u2] = acc;
        }
        __syncwarp();
#pragma unroll
        for (int u2 = 0; u2 < 7; u2++) {
            const int u = ub + u2;
            const int srow = 2 * u + jp;
            if (u < 25 && srow < 49) myrow[srow * 16 + d8] = a[u2];
        }
        __syncwarp();
    }

    // ---------------- softmax2: rotated access ----------------
    {
        const int r2 = (t >> 1) & 1;
#pragma unroll 1
        for (int s = t; s < 49; s += 16) {
            float4* row = reinterpret_cast<float4*>(&myrow[s * 16]);
            const int i0 = r2, i1 = r2 ^ 1;
            float4 v0 = row[i0], v1 = row[i1];
            float m = fmaxf(fmaxf(fmaxf(v0.x, v0.y), fmaxf(v0.z, v0.w)),
                            fmaxf(fmaxf(v1.x, v1.y), fmaxf(v1.z, v1.w)));
            v0.x = __expf(v0.x - m); v0.y = __expf(v0.y - m); v0.z = __expf(v0.z - m); v0.w = __expf(v0.w - m);
            v1.x = __expf(v1.x - m); v1.y = __expf(v1.y - m); v1.z = __expf(v1.z - m); v1.w = __expf(v1.w - m);
            float sum = (v0.x + v0.y + v0.z + v0.w) + (v1.x + v1.y + v1.z + v1.w);
            float inv = 1.f / sum;
            v0.x *= inv; v0.y *= inv; v0.z *= inv; v0.w *= inv;
            v1.x *= inv; v1.y *= inv; v1.z *= inv; v1.w *= inv;
            row[i0] = v0; row[i1] = v1;
        }
    }

    // ---------------- FC head: two K-halves, 4 accumulators ----------------
    float ac0 = sh[SM_F1B + t], ac1 = 0.f, ac2 = 0.f, ac3 = 0.f;
    __syncthreads();
    for (int idx = tid; idx < 768; idx += NTHR) {    // 16 rows x 48 float4 (cols 0..191)
        int j = idx / 48, c4 = idx - j * 48;
        *reinterpret_cast<float4*>(&sh[SM_QB + j * 204 + c4 * 4]) =
            *reinterpret_cast<const float4*>(&fc1w[j * 392 + c4 * 4]);
    }
    __syncthreads();
#pragma unroll 1
    for (int s = 0; s < 24; s += 2) {
        float4 a0 = *reinterpret_cast<const float4*>(&myrow[s * 16]);
        float4 a1 = *reinterpret_cast<const float4*>(&myrow[s * 16 + 4]);
        float4 w0 = *reinterpret_cast<const float4*>(&sh[SM_QB + t * 204 + s * 8]);
        float4 w1 = *reinterpret_cast<const float4*>(&sh[SM_QB + t * 204 + s * 8 + 4]);
        float4 a2 = *reinterpret_cast<const float4*>(&myrow[(s + 1) * 16]);
        float4 a3 = *reinterpret_cast<const float4*>(&myrow[(s + 1) * 16 + 4]);
        float4 w2 = *reinterpret_cast<const float4*>(&sh[SM_QB + t * 204 + (s + 1) * 8]);
        float4 w3 = *reinterpret_cast<const float4*>(&sh[SM_QB + t * 204 + (s + 1) * 8 + 4]);
        ac0 = dot4(w0, a0, ac0); ac1 = dot4(w1, a1, ac1);
        ac2 = dot4(w2, a2, ac2); ac3 = dot4(w3, a3, ac3);
    }
    __syncthreads();
    for (int idx = tid; idx < 800; idx += NTHR) {    // 16 rows x 50 float4 (cols 192..391)
        int j = idx / 50, c4 = idx - j * 50;
        *reinterpret_cast<float4*>(&sh[SM_QB + j * 204 + c4 * 4]) =
            *reinterpret_cast<const float4*>(&fc1w[j * 392 + 192 + c4 * 4]);
    }
    __syncthreads();
#pragma unroll 1
    for (int s = 24; s < 48; s += 2) {
        float4 a0 = *reinterpret_cast<const float4*>(&myrow[s * 16]);
        float4 a1 = *reinterpret_cast<const float4*>(&myrow[s * 16 + 4]);
        float4 w0 = *reinterpret_cast<const float4*>(&sh[SM_QB + t * 204 + (s - 24) * 8]);
        float4 w1 = *reinterpret_cast<const float4*>(&sh[SM_QB + t * 204 + (s - 24) * 8 + 4]);
        float4 a2 = *reinterpret_cast<const float4*>(&myrow[(s + 1) * 16]);
        float4 a3 = *reinterpret_cast<const float4*>(&myrow[(s + 1) * 16 + 4]);
        float4 w2 = *reinterpret_cast<const float4*>(&sh[SM_QB + t * 204 + (s - 23) * 8]);
        float4 w3 = *reinterpret_cast<const float4*>(&sh[SM_QB + t * 204 + (s - 23) * 8 + 4]);
        ac0 = dot4(w0, a0, ac0); ac1 = dot4(w1, a1, ac1);
        ac2 = dot4(w2, a2, ac2); ac3 = dot4(w3, a3, ac3);
    }
    {   // s = 48 tail
        float4 a0 = *reinterpret_cast<const float4*>(&myrow[48 * 16]);
        float4 a1 = *reinterpret_cast<const float4*>(&myrow[48 * 16 + 4]);
        float4 w0 = *reinterpret_cast<const float4*>(&sh[SM_QB + t * 204 + 24 * 8]);
        float4 w1 = *reinterpret_cast<const float4*>(&sh[SM_QB + t * 204 + 24 * 8 + 4]);
        ac0 = dot4(w0, a0, ac0); ac1 = dot4(w1, a1, ac1);
    }
    sh[SM_H + ls * 16 + t] = fmaxf((ac0 + ac1) + (ac2 + ac3), 0.f);
    __syncwarp();

    {
        float lg = 0.f;
        if (t < 10) {
            const float4* w  = reinterpret_cast<const float4*>(&sh[SM_F2W + t * 16]);
            const float4* hh = reinterpret_cast<const float4*>(&sh[SM_H + ls * 16]);
            lg = dot4(w[0], hh[0], lg); lg = dot4(w[1], hh[1], lg);
            lg = dot4(w[2], hh[2], lg); lg = dot4(w[3], hh[3], lg);
            lg += sh[SM_F2B + t];
        }
        sh[SM_LG + ls * 16 + t] = lg;
    }
    __syncwarp();

    if (t == 0 && b < B) {
        const float* lrow = &sh[SM_LG + ls * 16];
        float m = lrow[0];
#pragma unroll
        for (int c = 1; c < 10; c++) m = fmaxf(m, lrow[c]);
        float ex[10], sum = 0.f;
#pragma unroll
        for (int c = 0; c < 10; c++) { ex[c] = __expf(lrow[c] - m); sum += ex[c]; }
        float inv = 1.f / sum;
        float* o = out + (size_t)b * 10;
#pragma unroll
        for (int c = 0; c < 10; c++) o[c] = ex[c] * inv;
    }
}

extern "C" void kernel_launch(void* const* d_in, const int* in_sizes, int n_in,
                              void* d_out, int out_size) {
    const float* x   = (const float*)d_in[0];
    const float* pe  = (const float*)d_in[1];
    const float* WQ1 = (const float*)d_in[2];
    const float* WK1 = (const float*)d_in[3];
    const float* WV1 = (const float*)d_in[4];
    const float* WQ2 = (const float*)d_in[5];
    const float* WK2 = (const float*)d_in[6];
    const float* WV2 = (const float*)d_in[7];
    const float* f1w = (const float*)d_in[8];
    const float* f1b = (const float*)d_in[9];
    const float* f2w = (const float*)d_in[10];
    const float* f2b = (const float*)d_in[11];
    float* out = (float*)d_out;

    int B = in_sizes[0] / (3 * 28 * 28);
    int grid = (B + GRP - 1) / GRP;
    size_t smem = (size_t)SM_TOT * sizeof(float);

    cudaFuncSetAttribute(vit_fused_kernel,
                         cudaFuncAttributeMaxDynamicSharedMemorySize, (int)smem);
    vit_fused_kernel<<<grid, NTHR, smem>>>(x, pe, WQ1, WK1, WV1, WQ2, WK2, WV2,
                                           f1w, f1b, f2w, f2b, out, B);
}